// round 15
// baseline (speedup 1.0000x reference)
#include <cuda_runtime.h>
#include <cuda_bf16.h>
#include <cstdint>

#define Bc 16
#define Sc 512
#define Dc 768
#define Lc 20
#define NEGF 1000000000000.0f

typedef unsigned long long ull;
typedef unsigned int u32;

// ---------------- scratch (no allocation allowed) ----------------
__device__ float g_q[Bc * Sc * 64];        // RoPE'd q, pre-scaled by 1/8 (exact)
__device__ float g_k[Bc * Sc * 64];
__device__ float g_bn[Bc * Lc * Sc];       // dense[b,2l,n]/2
__device__ float g_bm[Bc * Lc * Sc];       // dense[b,2l+1,m]/2
__device__ __nv_bfloat16 gB_h[192 * 768];  // split W^T
__device__ __nv_bfloat16 gB_l[192 * 768];

// ---------------- helpers ----------------
__device__ __forceinline__ ull fma2(ull a, ull b, ull c) {
    ull d; asm("fma.rn.f32x2 %0, %1, %2, %3;" : "=l"(d) : "l"(a), "l"(b), "l"(c)); return d;
}
__device__ __forceinline__ ull add2(ull a, ull b) {
    ull d; asm("add.rn.f32x2 %0, %1, %2;" : "=l"(d) : "l"(a), "l"(b)); return d;
}
__device__ __forceinline__ ull bcast2(float w) {
    ull d; u32 u = __float_as_uint(w);
    asm("mov.b64 %0, {%1, %1};" : "=l"(d) : "r"(u)); return d;
}
__device__ __forceinline__ ull pack2(float lo, float hi) {
    ull d; asm("mov.b64 %0, {%1, %2};" : "=l"(d) : "f"(lo), "f"(hi)); return d;
}
__device__ __forceinline__ void unpack2(ull v, float& lo, float& hi) {
    asm("mov.b64 {%0, %1}, %2;" : "=f"(lo), "=f"(hi) : "l"(v));
}
__device__ __forceinline__ float fast_sigmoid(float v) {
    float t; asm("tanh.approx.f32 %0, %1;" : "=f"(t) : "f"(v * 0.5f));
    return fmaf(t, 0.5f, 0.5f);
}
__device__ __forceinline__ u32 smem_u32_of(const void* p) {
    u32 a; asm("{ .reg .u64 t; cvta.to.shared.u64 t, %1; cvt.u32.u64 %0, t; }" : "=r"(a) : "l"(p));
    return a;
}
__device__ __forceinline__ void ldm4(u32* r, u32 addr) {
    asm volatile("ldmatrix.sync.aligned.m8n8.x4.shared.b16 {%0,%1,%2,%3}, [%4];"
        : "=r"(r[0]), "=r"(r[1]), "=r"(r[2]), "=r"(r[3]) : "r"(addr));
}
__device__ __forceinline__ void mma_bf16(float* d, const u32* a, const u32* b) {
    asm volatile("mma.sync.aligned.m16n8k16.row.col.f32.bf16.bf16.f32 "
        "{%0,%1,%2,%3}, {%4,%5,%6,%7}, {%8,%9}, {%0,%1,%2,%3};"
        : "+f"(d[0]), "+f"(d[1]), "+f"(d[2]), "+f"(d[3])
        : "r"(a[0]), "r"(a[1]), "r"(a[2]), "r"(a[3]), "r"(b[0]), "r"(b[1]));
}
__device__ __forceinline__ u32 split_pair(float a, float b, u32& lw) {
    __nv_bfloat16 h0 = __float2bfloat16_rn(a);
    __nv_bfloat16 h1 = __float2bfloat16_rn(b);
    __nv_bfloat16 l0 = __float2bfloat16_rn(a - __bfloat162float(h0));
    __nv_bfloat16 l1 = __float2bfloat16_rn(b - __bfloat162float(h1));
    lw = (u32)__bfloat16_as_ushort(l0) | ((u32)__bfloat16_as_ushort(l1) << 16);
    return (u32)__bfloat16_as_ushort(h0) | ((u32)__bfloat16_as_ushort(h1) << 16);
}

// ---------------- kernel W: constant writer, 448 tiles (tm>tn) ---------------
// Dummy 77KB dynamic smem caps residency at 2 blocks/SM, leaving room for one
// gemm block (72KB / 256 thr) or two phase2 blocks (2x35KB) to co-run.
#define WRITER_SMEM 78848

__global__ void __launch_bounds__(256) writer_kernel(
    const int* __restrict__ am, float* __restrict__ out)
{
    extern __shared__ char wsm[];
    int* mMs = reinterpret_cast<int*>(wsm);
    int* mNs = mMs + 64;
    const size_t PROB_OFF = (size_t)Bc * Lc * Sc * Sc;
    int tid = threadIdx.x;
    int f = blockIdx.x;                  // 0..447
    int b = f / 28, p = f % 28;
    int tm = 1;
    while (p >= tm) { p -= tm; tm++; }   // tm 1..7, tn = p < tm
    int tn = p;
    int m0 = tm * 64, n0 = tn * 64;
    if (tid < 64) {
        mMs[tid] = am[b * Sc + m0 + tid];
        mNs[tid] = am[b * Sc + n0 + tid];
    }
    __syncthreads();
    float4 lv[4];
    int rowv[4], pv_[4];
    #pragma unroll
    for (int t = 0; t < 4; t++) {
        int idx = tid + t * 256;          // 1024 = 64 rows x 16 float4
        int row = idx >> 4, pp = idx & 15;
        rowv[t] = row; pv_[t] = pp;
        int mmv = mMs[row];
        lv[t].x = (mmv && mNs[pp * 4 + 0]) ? -NEGF : -2.0f * NEGF;
        lv[t].y = (mmv && mNs[pp * 4 + 1]) ? -NEGF : -2.0f * NEGF;
        lv[t].z = (mmv && mNs[pp * 4 + 2]) ? -NEGF : -2.0f * NEGF;
        lv[t].w = (mmv && mNs[pp * 4 + 3]) ? -NEGF : -2.0f * NEGF;
    }
    float4 z4 = make_float4(0.f, 0.f, 0.f, 0.f);
    size_t base = (((size_t)(b * Lc)) * Sc + m0) * (size_t)Sc + n0;
    for (int l = 0; l < Lc; l++) {
        #pragma unroll
        for (int t = 0; t < 4; t++) {
            size_t o = base + (size_t)rowv[t] * Sc + pv_[t] * 4;
            __stcs(reinterpret_cast<float4*>(out + o), lv[t]);
            __stcs(reinterpret_cast<float4*>(out + PROB_OFF + o), z4);
        }
        base += (size_t)Sc * Sc;
    }
}

// ---------------- kernel S: split W^T [192][768] into bf16 hi/lo ------------
__global__ void __launch_bounds__(256) split_w_kernel(
    const float* __restrict__ w1, const float* __restrict__ w2)
{
    int idx = blockIdx.x * 256 + threadIdx.x;          // 18432 = 192*96 uint4
    int r = idx / 96, kg = idx % 96;
    u32 hw[4], lw[4];
    #pragma unroll
    for (int j = 0; j < 4; j++) {
        float va, vb;
        int k = kg * 8 + 2 * j;
        if (r < 128)      { va = w1[(size_t)k * 128 + r]; vb = w1[(size_t)(k+1) * 128 + r]; }
        else if (r < 168) { va = w2[(size_t)k * 40 + (r-128)]; vb = w2[(size_t)(k+1) * 40 + (r-128)]; }
        else              { va = 0.f; vb = 0.f; }
        hw[j] = split_pair(va, vb, lw[j]);
    }
    reinterpret_cast<uint4*>(gB_h)[idx] = make_uint4(hw[0], hw[1], hw[2], hw[3]);
    reinterpret_cast<uint4*>(gB_l)[idx] = make_uint4(lw[0], lw[1], lw[2], lw[3]);
}

// ---------------- kernel G: HMMA GEMM (M=64/CTA, N=192, K=768) + epilogue ---
#define AH_OFF 0
#define AL_OFF 9216
#define BH_OFF 18432
#define BL_OFF 46080
#define GEMM_SMEM 73728      // >= max(tiles 73728, D 64*196*4=50176)

__global__ void __launch_bounds__(256) gemm_kernel(
    const float* __restrict__ x,
    const float* __restrict__ b1, const float* __restrict__ b2)
{
    extern __shared__ char smem[];
    u32 smem_u = smem_u32_of(smem);
    int tid = threadIdx.x;
    int wid = tid >> 5, lane = tid & 31;
    int rowTile = blockIdx.x;
    int wm = wid & 3, wn = wid >> 2;

    float acc[12][4];
    #pragma unroll
    for (int j = 0; j < 12; j++)
        #pragma unroll
        for (int q = 0; q < 4; q++) acc[j][q] = 0.f;

    int rr = lane & 7, qq = lane >> 3;
    u32 aoff = (u32)((rr + (qq & 1) * 8) * 144 + (qq >> 1) * 16);
    u32 boff = (u32)((rr + (qq >> 1) * 8) * 144 + (qq & 1) * 16);
    u32 aBaseH = smem_u + AH_OFF + wm * 16 * 144 + aoff;
    u32 aBaseL = smem_u + AL_OFF + wm * 16 * 144 + aoff;
    u32 bBaseH = smem_u + BH_OFF + wn * 96 * 144 + boff;
    u32 bBaseL = smem_u + BL_OFF + wn * 96 * 144 + boff;

    const uint4* srcBh = reinterpret_cast<const uint4*>(gB_h);
    const uint4* srcBl = reinterpret_cast<const uint4*>(gB_l);

    for (int kt = 0; kt < 12; kt++) {
        if (kt) __syncthreads();
        // A: read x fp32 directly, split in-register, store bf16 h/l to smem
        #pragma unroll
        for (int t = 0; t < 4; t++) {
            int idx = tid + t * 256;           // 1024 = 64 rows x 16 float4
            int r = idx >> 4, c4 = idx & 15;
            float4 v = *reinterpret_cast<const float4*>(
                x + (size_t)(rowTile * 64 + r) * Dc + kt * 64 + c4 * 4);
            u32 l0, l1;
            u32 h0 = split_pair(v.x, v.y, l0);
            u32 h1 = split_pair(v.z, v.w, l1);
            *reinterpret_cast<uint2*>(smem + AH_OFF + r * 144 + c4 * 8) = make_uint2(h0, h1);
            *reinterpret_cast<uint2*>(smem + AL_OFF + r * 144 + c4 * 8) = make_uint2(l0, l1);
        }
        // B: 192 rows x 8 uint4 from pre-split global
        #pragma unroll
        for (int t = 0; t < 6; t++) {
            int idx = tid + t * 256;
            int r = idx >> 3, c8 = idx & 7;
            size_t gi = (size_t)r * 96 + kt * 8 + c8;
            *reinterpret_cast<uint4*>(smem + BH_OFF + r * 144 + c8 * 16) = srcBh[gi];
            *reinterpret_cast<uint4*>(smem + BL_OFF + r * 144 + c8 * 16) = srcBl[gi];
        }
        __syncthreads();

        #pragma unroll
        for (int ks = 0; ks < 4; ks++) {
            u32 ah[4], al[4];
            ldm4(ah, aBaseH + ks * 32);
            ldm4(al, aBaseL + ks * 32);
            #pragma unroll
            for (int g = 0; g < 6; g++) {
                u32 bh[4], bl[4];
                ldm4(bh, bBaseH + g * 2304 + ks * 32);   // 16 rows * 144B
                ldm4(bl, bBaseL + g * 2304 + ks * 32);
                mma_bf16(acc[2*g],     ah, bh);
                mma_bf16(acc[2*g + 1], ah, bh + 2);
                mma_bf16(acc[2*g],     ah, bl);
                mma_bf16(acc[2*g + 1], ah, bl + 2);
                mma_bf16(acc[2*g],     al, bh);
                mma_bf16(acc[2*g + 1], al, bh + 2);
            }
        }
    }

    // dump accumulators to smem D[64][196] f32
    __syncthreads();
    float* Ds = reinterpret_cast<float*>(smem);
    {
        int mrow = wm * 16 + (lane >> 2);
        int ncol0 = wn * 96 + (lane & 3) * 2;
        #pragma unroll
        for (int j = 0; j < 12; j++) {
            int n = ncol0 + j * 8;
            *reinterpret_cast<float2*>(&Ds[mrow * 196 + n])       = make_float2(acc[j][0], acc[j][1]);
            *reinterpret_cast<float2*>(&Ds[(mrow + 8) * 196 + n]) = make_float2(acc[j][2], acc[j][3]);
        }
    }
    __syncthreads();

    // epilogue: bias + RoPE + scatter (each thread: 1 row, 48 cols)
    int row_l = (wid & 1) * 32 + lane;
    int colbase = (wid >> 1) * 48;
    int grow = rowTile * 64 + row_l;
    int b = grow >> 9, s = grow & 511;
    float fs = (float)s;

    #pragma unroll
    for (int g = 0; g < 12; g++) {
        int c = colbase + g * 4;
        float4 vv = *reinterpret_cast<const float4*>(&Ds[row_l * 196 + c]);
        float v0 = vv.x, v1 = vv.y, v2 = vv.z, v3 = vv.w;
        if (c < 128) {
            float4 bb = *reinterpret_cast<const float4*>(b1 + c);
            v0 += bb.x; v1 += bb.y; v2 += bb.z; v3 += bb.w;
            int i = c >> 2;
            float fq = exp2f(-(float)i * 0.41524101186092036f);
            float sn, cs;
            sincosf(fs * fq, &sn, &cs);
            float q0 = v0 * cs - v2 * sn, q1 = v2 * cs + v0 * sn;
            float k0 = v1 * cs - v3 * sn, k1 = v3 * cs + v1 * sn;
            *reinterpret_cast<float2*>(g_q + (size_t)grow * 64 + 2 * i) =
                make_float2(q0 * 0.125f, q1 * 0.125f);
            *reinterpret_cast<float2*>(g_k + (size_t)grow * 64 + 2 * i) =
                make_float2(k0, k1);
        } else if (c < 168) {
            int cc = c - 128;
            float4 bb = *reinterpret_cast<const float4*>(b2 + cc);
            int l0 = cc >> 1;
            size_t o = (size_t)(b * Lc + l0) * Sc + s;
            g_bn[o]      = (v0 + bb.x) * 0.5f;
            g_bm[o]      = (v1 + bb.y) * 0.5f;
            g_bn[o + Sc] = (v2 + bb.z) * 0.5f;
            g_bm[o + Sc] = (v3 + bb.w) * 0.5f;
        }
    }
}

// ---------------- kernel P: compute tiles only (tm <= tn), all 20 L ---------
__global__ void __launch_bounds__(256, 4) phase2_kernel(
    const int* __restrict__ am, float* __restrict__ out)
{
    __shared__ float qT[64][68];
    __shared__ float kT[64][68];
    __shared__ int   mMs[64], mNs[64];

    const size_t PROB_OFF = (size_t)Bc * Lc * Sc * Sc;
    int b = blockIdx.y;
    int tmv = 0, tt = blockIdx.x;                 // 36 upper-tri tiles
    while (tt >= 8 - tmv) { tt -= 8 - tmv; tmv++; }
    int tnv = tmv + tt;

    int tid = threadIdx.x;
    int m0 = tmv * 64, n0 = tnv * 64;
    const float* qb = g_q + (size_t)b * Sc * 64;
    const float* kb = g_k + (size_t)b * Sc * 64;

    #pragma unroll
    for (int t = 0; t < 16; t++) {
        int idx = tid + t * 256;
        int r = idx >> 6, kk = idx & 63;
        qT[kk][r] = qb[(size_t)(m0 + r) * 64 + kk];
        kT[kk][r] = kb[(size_t)(n0 + r) * 64 + kk];
    }
    if (tid < 64) {
        mMs[tid] = am[b * Sc + m0 + tid];
        mNs[tid] = am[b * Sc + n0 + tid];
    }
    __syncthreads();

    int tx = tid & 15, ty = tid >> 4;
    int nl = tx * 4, ml = ty * 4;

    ull acc2[4][2];
    #pragma unroll
    for (int i = 0; i < 4; i++) { acc2[i][0] = 0ull; acc2[i][1] = 0ull; }

    #pragma unroll 4
    for (int kk = 0; kk < 64; kk++) {
        float4 qv = *reinterpret_cast<const float4*>(&qT[kk][ml]);
        float4 kv = *reinterpret_cast<const float4*>(&kT[kk][nl]);
        ull k01 = pack2(kv.x, kv.y);
        ull k23 = pack2(kv.z, kv.w);
        ull q0 = bcast2(qv.x), q1 = bcast2(qv.y), q2 = bcast2(qv.z), q3 = bcast2(qv.w);
        acc2[0][0] = fma2(q0, k01, acc2[0][0]); acc2[0][1] = fma2(q0, k23, acc2[0][1]);
        acc2[1][0] = fma2(q1, k01, acc2[1][0]); acc2[1][1] = fma2(q1, k23, acc2[1][1]);
        acc2[2][0] = fma2(q2, k01, acc2[2][0]); acc2[2][1] = fma2(q2, k23, acc2[2][1]);
        acc2[3][0] = fma2(q3, k01, acc2[3][0]); acc2[3][1] = fma2(q3, k23, acc2[3][1]);
    }

    int mm[4], mn[4];
    #pragma unroll
    for (int i = 0; i < 4; i++) mm[i] = mMs[ml + i];
    #pragma unroll
    for (int j = 0; j < 4; j++) mn[j] = mNs[nl + j];

    float* probs = out + PROB_OFF;
    int gm0 = m0 + ml, gn0 = n0 + nl;
    size_t rowbase = (((size_t)(b * Lc)) * Sc + gm0) * (size_t)Sc + gn0;

    const float* bn_ptr = g_bn + (size_t)b * Lc * Sc + n0 + nl;
    const float* bm_ptr = g_bm + (size_t)b * Lc * Sc + m0 + ml;

    float4 bn_cur = __ldg(reinterpret_cast<const float4*>(bn_ptr));
    float4 bm_cur = __ldg(reinterpret_cast<const float4*>(bm_ptr));

    for (int l = 0; l < Lc; l++) {
        float4 bn_nxt, bm_nxt;
        if (l < Lc - 1) {
            bn_nxt = __ldg(reinterpret_cast<const float4*>(bn_ptr + (size_t)(l + 1) * Sc));
            bm_nxt = __ldg(reinterpret_cast<const float4*>(bm_ptr + (size_t)(l + 1) * Sc));
        }
        ull bn01 = pack2(bn_cur.x, bn_cur.y);
        ull bn23 = pack2(bn_cur.z, bn_cur.w);
        float bmv[4] = {bm_cur.x, bm_cur.y, bm_cur.z, bm_cur.w};
        #pragma unroll
        for (int i = 0; i < 4; i++) {
            int gm = gm0 + i;
            ull bm2 = bcast2(bmv[i]);
            ull v01 = add2(add2(acc2[i][0], bn01), bm2);
            ull v23 = add2(add2(acc2[i][1], bn23), bm2);
            float v[4];
            unpack2(v01, v[0], v[1]);
            unpack2(v23, v[2], v[3]);
            float lv[4], pv[4];
            #pragma unroll
            for (int j = 0; j < 4; j++) {
                float xv = (mm[i] && mn[j]) ? v[j] : -NEGF;
                if (gm > gn0 + j) xv -= NEGF;
                lv[j] = xv;
                pv[j] = fast_sigmoid(xv);
            }
            size_t o = rowbase + (size_t)i * Sc;
            __stcs(reinterpret_cast<float4*>(out + o),
                   make_float4(lv[0], lv[1], lv[2], lv[3]));
            __stcs(reinterpret_cast<float4*>(probs + o),
                   make_float4(pv[0], pv[1], pv[2], pv[3]));
        }
        bn_cur = bn_nxt;
        bm_cur = bm_nxt;
        rowbase += (size_t)Sc * Sc;
    }
}

// ---------------- launcher: forked-graph pipeline with capped writer --------
extern "C" void kernel_launch(void* const* d_in, const int* in_sizes, int n_in,
                              void* d_out, int out_size) {
    (void)in_sizes; (void)n_in; (void)out_size;
    const float* x  = (const float*)d_in[0];
    const int*   am = (const int*)  d_in[1];
    const float* w1 = (const float*)d_in[2];
    const float* b1 = (const float*)d_in[3];
    const float* w2 = (const float*)d_in[4];
    const float* b2 = (const float*)d_in[5];
    float* out = (float*)d_out;

    static cudaStream_t sB = nullptr;
    static cudaEvent_t evFork = nullptr, evJoin = nullptr;
    if (!sB) {
        cudaStreamCreateWithFlags(&sB, cudaStreamNonBlocking);
        cudaEventCreateWithFlags(&evFork, cudaEventDisableTiming);
        cudaEventCreateWithFlags(&evJoin, cudaEventDisableTiming);
        cudaFuncSetAttribute(gemm_kernel,
                             cudaFuncAttributeMaxDynamicSharedMemorySize, GEMM_SMEM);
        cudaFuncSetAttribute(writer_kernel,
                             cudaFuncAttributeMaxDynamicSharedMemorySize, WRITER_SMEM);
    }

    // fork: writer branch (depends only on am), occupancy-capped at 2/SM
    cudaEventRecord(evFork, 0);
    cudaStreamWaitEvent(sB, evFork, 0);
    writer_kernel<<<448, 256, WRITER_SMEM, sB>>>(am, out);

    // main branch: split W -> gemm -> phase2 compute
    split_w_kernel<<<72, 256>>>(w1, w2);
    gemm_kernel<<<128, 256, GEMM_SMEM>>>(x, b1, b2);
    dim3 g2(36, 16);
    phase2_kernel<<<g2, 256>>>(am, out);

    // join writer branch back into stream 0
    cudaEventRecord(evJoin, sB);
    cudaStreamWaitEvent(0, evJoin, 0);
}

// round 16
// speedup vs baseline: 1.0177x; 1.0177x over previous
#include <cuda_runtime.h>
#include <cuda_bf16.h>
#include <cstdint>

#define Bc 16
#define Sc 512
#define Dc 768
#define Lc 20
#define NEGF 1000000000000.0f

typedef unsigned long long ull;
typedef unsigned int u32;

// ---------------- scratch (no allocation allowed) ----------------
__device__ float g_q[Bc * Sc * 64];        // RoPE'd q, pre-scaled by 1/8 (exact)
__device__ float g_k[Bc * Sc * 64];
__device__ float g_bn[Bc * Lc * Sc];       // dense[b,2l,n]/2
__device__ float g_bm[Bc * Lc * Sc];       // dense[b,2l+1,m]/2
__device__ __nv_bfloat16 gB_h[192 * 768];  // split W^T
__device__ __nv_bfloat16 gB_l[192 * 768];

// ---------------- helpers ----------------
__device__ __forceinline__ ull fma2(ull a, ull b, ull c) {
    ull d; asm("fma.rn.f32x2 %0, %1, %2, %3;" : "=l"(d) : "l"(a), "l"(b), "l"(c)); return d;
}
__device__ __forceinline__ ull add2(ull a, ull b) {
    ull d; asm("add.rn.f32x2 %0, %1, %2;" : "=l"(d) : "l"(a), "l"(b)); return d;
}
__device__ __forceinline__ ull bcast2(float w) {
    ull d; u32 u = __float_as_uint(w);
    asm("mov.b64 %0, {%1, %1};" : "=l"(d) : "r"(u)); return d;
}
__device__ __forceinline__ ull pack2(float lo, float hi) {
    ull d; asm("mov.b64 %0, {%1, %2};" : "=l"(d) : "f"(lo), "f"(hi)); return d;
}
__device__ __forceinline__ void unpack2(ull v, float& lo, float& hi) {
    asm("mov.b64 {%0, %1}, %2;" : "=f"(lo), "=f"(hi) : "l"(v));
}
__device__ __forceinline__ float fast_sigmoid(float v) {
    float t; asm("tanh.approx.f32 %0, %1;" : "=f"(t) : "f"(v * 0.5f));
    return fmaf(t, 0.5f, 0.5f);
}
__device__ __forceinline__ u32 smem_u32_of(const void* p) {
    u32 a; asm("{ .reg .u64 t; cvta.to.shared.u64 t, %1; cvt.u32.u64 %0, t; }" : "=r"(a) : "l"(p));
    return a;
}
__device__ __forceinline__ void ldm4(u32* r, u32 addr) {
    asm volatile("ldmatrix.sync.aligned.m8n8.x4.shared.b16 {%0,%1,%2,%3}, [%4];"
        : "=r"(r[0]), "=r"(r[1]), "=r"(r[2]), "=r"(r[3]) : "r"(addr));
}
__device__ __forceinline__ void mma_bf16(float* d, const u32* a, const u32* b) {
    asm volatile("mma.sync.aligned.m16n8k16.row.col.f32.bf16.bf16.f32 "
        "{%0,%1,%2,%3}, {%4,%5,%6,%7}, {%8,%9}, {%0,%1,%2,%3};"
        : "+f"(d[0]), "+f"(d[1]), "+f"(d[2]), "+f"(d[3])
        : "r"(a[0]), "r"(a[1]), "r"(a[2]), "r"(a[3]), "r"(b[0]), "r"(b[1]));
}
__device__ __forceinline__ u32 split_pair(float a, float b, u32& lw) {
    __nv_bfloat16 h0 = __float2bfloat16_rn(a);
    __nv_bfloat16 h1 = __float2bfloat16_rn(b);
    __nv_bfloat16 l0 = __float2bfloat16_rn(a - __bfloat162float(h0));
    __nv_bfloat16 l1 = __float2bfloat16_rn(b - __bfloat162float(h1));
    lw = (u32)__bfloat16_as_ushort(l0) | ((u32)__bfloat16_as_ushort(l1) << 16);
    return (u32)__bfloat16_as_ushort(h0) | ((u32)__bfloat16_as_ushort(h1) << 16);
}

// ---------------- shared writer body: const tile f (tm>tn), all 20 L --------
__device__ __forceinline__ void writer_body(
    int f, int tid, const int* __restrict__ am, float* __restrict__ out,
    int* mMs, int* mNs)
{
    const size_t PROB_OFF = (size_t)Bc * Lc * Sc * Sc;
    int b = f / 28, p = f % 28;
    int tm = 1;
    while (p >= tm) { p -= tm; tm++; }   // tm 1..7, tn = p < tm
    int tn = p;
    int m0 = tm * 64, n0 = tn * 64;
    if (tid < 64) {
        mMs[tid] = am[b * Sc + m0 + tid];
        mNs[tid] = am[b * Sc + n0 + tid];
    }
    __syncthreads();
    float4 lv[4];
    int rowv[4], pv_[4];
    #pragma unroll
    for (int t = 0; t < 4; t++) {
        int idx = tid + t * 256;          // 1024 = 64 rows x 16 float4
        int row = idx >> 4, pp = idx & 15;
        rowv[t] = row; pv_[t] = pp;
        int mmv = mMs[row];
        lv[t].x = (mmv && mNs[pp * 4 + 0]) ? -NEGF : -2.0f * NEGF;
        lv[t].y = (mmv && mNs[pp * 4 + 1]) ? -NEGF : -2.0f * NEGF;
        lv[t].z = (mmv && mNs[pp * 4 + 2]) ? -NEGF : -2.0f * NEGF;
        lv[t].w = (mmv && mNs[pp * 4 + 3]) ? -NEGF : -2.0f * NEGF;
    }
    float4 z4 = make_float4(0.f, 0.f, 0.f, 0.f);
    size_t base = (((size_t)(b * Lc)) * Sc + m0) * (size_t)Sc + n0;
    for (int l = 0; l < Lc; l++) {
        #pragma unroll
        for (int t = 0; t < 4; t++) {
            size_t o = base + (size_t)rowv[t] * Sc + pv_[t] * 4;
            __stcs(reinterpret_cast<float4*>(out + o), lv[t]);
            __stcs(reinterpret_cast<float4*>(out + PROB_OFF + o), z4);
        }
        base += (size_t)Sc * Sc;
    }
}

// ---------------- kernel S: split W^T [192][768] into bf16 hi/lo ------------
__global__ void __launch_bounds__(256) split_w_kernel(
    const float* __restrict__ w1, const float* __restrict__ w2)
{
    int idx = blockIdx.x * 256 + threadIdx.x;          // 18432 = 192*96 uint4
    int r = idx / 96, kg = idx % 96;
    u32 hw[4], lw[4];
    #pragma unroll
    for (int j = 0; j < 4; j++) {
        float va, vb;
        int k = kg * 8 + 2 * j;
        if (r < 128)      { va = w1[(size_t)k * 128 + r]; vb = w1[(size_t)(k+1) * 128 + r]; }
        else if (r < 168) { va = w2[(size_t)k * 40 + (r-128)]; vb = w2[(size_t)(k+1) * 40 + (r-128)]; }
        else              { va = 0.f; vb = 0.f; }
        hw[j] = split_pair(va, vb, lw[j]);
    }
    reinterpret_cast<uint4*>(gB_h)[idx] = make_uint4(hw[0], hw[1], hw[2], hw[3]);
    reinterpret_cast<uint4*>(gB_l)[idx] = make_uint4(lw[0], lw[1], lw[2], lw[3]);
}

// ---------------- kernel M (mega2): gemm blocks 0..127 || 250 writer tiles --
#define AH_OFF 0
#define AL_OFF 9216
#define BH_OFF 18432
#define BL_OFF 46080
#define GEMM_SMEM 73728      // >= max(tiles 73728, D 64*196*4=50176)
#define MEGA_WRITERS 250     // const tiles handled here (f = 0..249)

__global__ void __launch_bounds__(256) mega2_kernel(
    const float* __restrict__ x, const int* __restrict__ am,
    const float* __restrict__ b1, const float* __restrict__ b2,
    float* __restrict__ out)
{
    extern __shared__ char smem[];
    int tid = threadIdx.x;

    if (blockIdx.x >= 128) {
        // ---------------- constant writer tiles f = 0..249 ----------------
        int* mMs = reinterpret_cast<int*>(smem);
        int* mNs = mMs + 64;
        writer_body((int)blockIdx.x - 128, tid, am, out, mMs, mNs);
        return;
    }

    // ---------------- GEMM path (rowTile = blockIdx.x) ------------------------
    u32 smem_u = smem_u32_of(smem);
    int wid = tid >> 5, lane = tid & 31;
    int rowTile = blockIdx.x;
    int wm = wid & 3, wn = wid >> 2;

    float acc[12][4];
    #pragma unroll
    for (int j = 0; j < 12; j++)
        #pragma unroll
        for (int q = 0; q < 4; q++) acc[j][q] = 0.f;

    int rr = lane & 7, qq = lane >> 3;
    u32 aoff = (u32)((rr + (qq & 1) * 8) * 144 + (qq >> 1) * 16);
    u32 boff = (u32)((rr + (qq >> 1) * 8) * 144 + (qq & 1) * 16);
    u32 aBaseH = smem_u + AH_OFF + wm * 16 * 144 + aoff;
    u32 aBaseL = smem_u + AL_OFF + wm * 16 * 144 + aoff;
    u32 bBaseH = smem_u + BH_OFF + wn * 96 * 144 + boff;
    u32 bBaseL = smem_u + BL_OFF + wn * 96 * 144 + boff;

    const uint4* srcBh = reinterpret_cast<const uint4*>(gB_h);
    const uint4* srcBl = reinterpret_cast<const uint4*>(gB_l);

    for (int kt = 0; kt < 12; kt++) {
        if (kt) __syncthreads();
        // A: read x fp32 directly, split in-register, store bf16 h/l to smem
        #pragma unroll
        for (int t = 0; t < 4; t++) {
            int idx = tid + t * 256;           // 1024 = 64 rows x 16 float4
            int r = idx >> 4, c4 = idx & 15;
            float4 v = *reinterpret_cast<const float4*>(
                x + (size_t)(rowTile * 64 + r) * Dc + kt * 64 + c4 * 4);
            u32 l0, l1;
            u32 h0 = split_pair(v.x, v.y, l0);
            u32 h1 = split_pair(v.z, v.w, l1);
            *reinterpret_cast<uint2*>(smem + AH_OFF + r * 144 + c4 * 8) = make_uint2(h0, h1);
            *reinterpret_cast<uint2*>(smem + AL_OFF + r * 144 + c4 * 8) = make_uint2(l0, l1);
        }
        // B: 192 rows x 8 uint4 from pre-split global
        #pragma unroll
        for (int t = 0; t < 6; t++) {
            int idx = tid + t * 256;
            int r = idx >> 3, c8 = idx & 7;
            size_t gi = (size_t)r * 96 + kt * 8 + c8;
            *reinterpret_cast<uint4*>(smem + BH_OFF + r * 144 + c8 * 16) = srcBh[gi];
            *reinterpret_cast<uint4*>(smem + BL_OFF + r * 144 + c8 * 16) = srcBl[gi];
        }
        __syncthreads();

        #pragma unroll
        for (int ks = 0; ks < 4; ks++) {
            u32 ah[4], al[4];
            ldm4(ah, aBaseH + ks * 32);
            ldm4(al, aBaseL + ks * 32);
            #pragma unroll
            for (int g = 0; g < 6; g++) {
                u32 bh[4], bl[4];
                ldm4(bh, bBaseH + g * 2304 + ks * 32);   // 16 rows * 144B
                ldm4(bl, bBaseL + g * 2304 + ks * 32);
                mma_bf16(acc[2*g],     ah, bh);
                mma_bf16(acc[2*g + 1], ah, bh + 2);
                mma_bf16(acc[2*g],     ah, bl);
                mma_bf16(acc[2*g + 1], ah, bl + 2);
                mma_bf16(acc[2*g],     al, bh);
                mma_bf16(acc[2*g + 1], al, bh + 2);
            }
        }
    }

    // dump accumulators to smem D[64][196] f32
    __syncthreads();
    float* Ds = reinterpret_cast<float*>(smem);
    {
        int mrow = wm * 16 + (lane >> 2);
        int ncol0 = wn * 96 + (lane & 3) * 2;
        #pragma unroll
        for (int j = 0; j < 12; j++) {
            int n = ncol0 + j * 8;
            *reinterpret_cast<float2*>(&Ds[mrow * 196 + n])       = make_float2(acc[j][0], acc[j][1]);
            *reinterpret_cast<float2*>(&Ds[(mrow + 8) * 196 + n]) = make_float2(acc[j][2], acc[j][3]);
        }
    }
    __syncthreads();

    // epilogue: bias + RoPE + scatter (each thread: 1 row, 48 cols)
    int row_l = (wid & 1) * 32 + lane;
    int colbase = (wid >> 1) * 48;
    int grow = rowTile * 64 + row_l;
    int b = grow >> 9, s = grow & 511;
    float fs = (float)s;

    #pragma unroll
    for (int g = 0; g < 12; g++) {
        int c = colbase + g * 4;
        float4 vv = *reinterpret_cast<const float4*>(&Ds[row_l * 196 + c]);
        float v0 = vv.x, v1 = vv.y, v2 = vv.z, v3 = vv.w;
        if (c < 128) {
            float4 bb = *reinterpret_cast<const float4*>(b1 + c);
            v0 += bb.x; v1 += bb.y; v2 += bb.z; v3 += bb.w;
            int i = c >> 2;
            float fq = exp2f(-(float)i * 0.41524101186092036f);
            float sn, cs;
            sincosf(fs * fq, &sn, &cs);
            float q0 = v0 * cs - v2 * sn, q1 = v2 * cs + v0 * sn;
            float k0 = v1 * cs - v3 * sn, k1 = v3 * cs + v1 * sn;
            *reinterpret_cast<float2*>(g_q + (size_t)grow * 64 + 2 * i) =
                make_float2(q0 * 0.125f, q1 * 0.125f);
            *reinterpret_cast<float2*>(g_k + (size_t)grow * 64 + 2 * i) =
                make_float2(k0, k1);
        } else if (c < 168) {
            int cc = c - 128;
            float4 bb = *reinterpret_cast<const float4*>(b2 + cc);
            int l0 = cc >> 1;
            size_t o = (size_t)(b * Lc + l0) * Sc + s;
            g_bn[o]      = (v0 + bb.x) * 0.5f;
            g_bm[o]      = (v1 + bb.y) * 0.5f;
            g_bn[o + Sc] = (v2 + bb.z) * 0.5f;
            g_bm[o + Sc] = (v3 + bb.w) * 0.5f;
        }
    }
}

// ---------------- kernel P (phase2full): 576 compute + 198 const tiles ------
__global__ void __launch_bounds__(256, 4) phase2full_kernel(
    const int* __restrict__ am, float* __restrict__ out)
{
    __shared__ float qT[64][68];
    __shared__ float kT[64][68];
    __shared__ int   mMs[64], mNs[64];

    const size_t PROB_OFF = (size_t)Bc * Lc * Sc * Sc;
    int pidx = blockIdx.x;
    int tid = threadIdx.x;

    if (pidx >= 576) {
        // const tiles f = 250..447
        writer_body(MEGA_WRITERS + pidx - 576, tid, am, out, mMs, mNs);
        return;
    }

    int b = pidx / 36, tt = pidx % 36;
    int tmv = 0;
    while (tt >= 8 - tmv) { tt -= 8 - tmv; tmv++; }
    int tnv = tmv + tt;
    int m0 = tmv * 64, n0 = tnv * 64;

    const float* qb = g_q + (size_t)b * Sc * 64;
    const float* kb = g_k + (size_t)b * Sc * 64;

    #pragma unroll
    for (int t = 0; t < 16; t++) {
        int idx = tid + t * 256;
        int r = idx >> 6, kk = idx & 63;
        qT[kk][r] = qb[(size_t)(m0 + r) * 64 + kk];
        kT[kk][r] = kb[(size_t)(n0 + r) * 64 + kk];
    }
    if (tid < 64) {
        mMs[tid] = am[b * Sc + m0 + tid];
        mNs[tid] = am[b * Sc + n0 + tid];
    }
    __syncthreads();

    int tx = tid & 15, ty = tid >> 4;
    int nl = tx * 4, ml = ty * 4;

    ull acc2[4][2];
    #pragma unroll
    for (int i = 0; i < 4; i++) { acc2[i][0] = 0ull; acc2[i][1] = 0ull; }

    #pragma unroll 4
    for (int kk = 0; kk < 64; kk++) {
        float4 qv = *reinterpret_cast<const float4*>(&qT[kk][ml]);
        float4 kv = *reinterpret_cast<const float4*>(&kT[kk][nl]);
        ull k01 = pack2(kv.x, kv.y);
        ull k23 = pack2(kv.z, kv.w);
        ull q0 = bcast2(qv.x), q1 = bcast2(qv.y), q2 = bcast2(qv.z), q3 = bcast2(qv.w);
        acc2[0][0] = fma2(q0, k01, acc2[0][0]); acc2[0][1] = fma2(q0, k23, acc2[0][1]);
        acc2[1][0] = fma2(q1, k01, acc2[1][0]); acc2[1][1] = fma2(q1, k23, acc2[1][1]);
        acc2[2][0] = fma2(q2, k01, acc2[2][0]); acc2[2][1] = fma2(q2, k23, acc2[2][1]);
        acc2[3][0] = fma2(q3, k01, acc2[3][0]); acc2[3][1] = fma2(q3, k23, acc2[3][1]);
    }

    int mm[4], mn[4];
    #pragma unroll
    for (int i = 0; i < 4; i++) mm[i] = mMs[ml + i];
    #pragma unroll
    for (int j = 0; j < 4; j++) mn[j] = mNs[nl + j];

    float* probs = out + PROB_OFF;
    int gm0 = m0 + ml, gn0 = n0 + nl;
    size_t rowbase = (((size_t)(b * Lc)) * Sc + gm0) * (size_t)Sc + gn0;

    const float* bn_ptr = g_bn + (size_t)b * Lc * Sc + n0 + nl;
    const float* bm_ptr = g_bm + (size_t)b * Lc * Sc + m0 + ml;

    float4 bn_cur = __ldg(reinterpret_cast<const float4*>(bn_ptr));
    float4 bm_cur = __ldg(reinterpret_cast<const float4*>(bm_ptr));

    for (int l = 0; l < Lc; l++) {
        float4 bn_nxt, bm_nxt;
        if (l < Lc - 1) {
            bn_nxt = __ldg(reinterpret_cast<const float4*>(bn_ptr + (size_t)(l + 1) * Sc));
            bm_nxt = __ldg(reinterpret_cast<const float4*>(bm_ptr + (size_t)(l + 1) * Sc));
        }
        ull bn01 = pack2(bn_cur.x, bn_cur.y);
        ull bn23 = pack2(bn_cur.z, bn_cur.w);
        float bmv[4] = {bm_cur.x, bm_cur.y, bm_cur.z, bm_cur.w};
        #pragma unroll
        for (int i = 0; i < 4; i++) {
            int gm = gm0 + i;
            ull bm2 = bcast2(bmv[i]);
            ull v01 = add2(add2(acc2[i][0], bn01), bm2);
            ull v23 = add2(add2(acc2[i][1], bn23), bm2);
            float v[4];
            unpack2(v01, v[0], v[1]);
            unpack2(v23, v[2], v[3]);
            float lv[4], pv[4];
            #pragma unroll
            for (int j = 0; j < 4; j++) {
                float xv = (mm[i] && mn[j]) ? v[j] : -NEGF;
                if (gm > gn0 + j) xv -= NEGF;
                lv[j] = xv;
                pv[j] = fast_sigmoid(xv);
            }
            size_t o = rowbase + (size_t)i * Sc;
            __stcs(reinterpret_cast<float4*>(out + o),
                   make_float4(lv[0], lv[1], lv[2], lv[3]));
            __stcs(reinterpret_cast<float4*>(probs + o),
                   make_float4(pv[0], pv[1], pv[2], pv[3]));
        }
        bn_cur = bn_nxt;
        bm_cur = bm_nxt;
        rowbase += (size_t)Sc * Sc;
    }
}

// ---------------- launcher: serial stream, in-kernel overlap ----------------
extern "C" void kernel_launch(void* const* d_in, const int* in_sizes, int n_in,
                              void* d_out, int out_size) {
    (void)in_sizes; (void)n_in; (void)out_size;
    const float* x  = (const float*)d_in[0];
    const int*   am = (const int*)  d_in[1];
    const float* w1 = (const float*)d_in[2];
    const float* b1 = (const float*)d_in[3];
    const float* w2 = (const float*)d_in[4];
    const float* b2 = (const float*)d_in[5];
    float* out = (float*)d_out;

    static int smem_set = 0;
    if (!smem_set) {
        cudaFuncSetAttribute(mega2_kernel,
                             cudaFuncAttributeMaxDynamicSharedMemorySize, GEMM_SMEM);
        smem_set = 1;
    }

    split_w_kernel<<<72, 256>>>(w1, w2);
    mega2_kernel<<<128 + MEGA_WRITERS, 256, GEMM_SMEM>>>(x, am, b1, b2, out);
    phase2full_kernel<<<576 + (448 - MEGA_WRITERS), 256>>>(am, out);
}